// round 8
// baseline (speedup 1.0000x reference)
#include <cuda_runtime.h>
#include <cuda_bf16.h>
#include <cstdint>

// Problem constants (fixed shapes from the reference)
#define H     40
#define KPTS  15
#define CIN   128
#define COUT  128
#define NMAX  20000
#define KDIM  (KPTS * CIN)   // 1920
#define KP_EXTENT_INV (1.0f / 1.2f)

// ---------------------------------------------------------------------------
// Static scratch: split-bf16 operands.
// A = weighted [N, 1920] as hi+lo bf16; B = weights^T [128, 1920] as hi+lo.
// ---------------------------------------------------------------------------
__device__ __nv_bfloat16 g_Ahi[(size_t)NMAX * KDIM];
__device__ __nv_bfloat16 g_Alo[(size_t)NMAX * KDIM];
__device__ __nv_bfloat16 g_Bhi[(size_t)COUT * KDIM];
__device__ __nv_bfloat16 g_Blo[(size_t)COUT * KDIM];

// ---------------------------------------------------------------------------
// PTX helpers
// ---------------------------------------------------------------------------
__device__ __forceinline__ uint32_t smem_u32(const void* p) {
    uint32_t a;
    asm("{ .reg .u64 t; cvta.to.shared.u64 t, %1; cvt.u32.u64 %0, t; }" : "=r"(a) : "l"(p));
    return a;
}
__device__ __forceinline__ void cp_async16(uint32_t dst, const void* src) {
    asm volatile("cp.async.cg.shared.global [%0], [%1], 16;\n" :: "r"(dst), "l"(src) : "memory");
}
__device__ __forceinline__ void cp_async_commit() {
    asm volatile("cp.async.commit_group;" ::: "memory");
}
template <int NN>
__device__ __forceinline__ void cp_async_wait() {
    asm volatile("cp.async.wait_group %0;" :: "n"(NN) : "memory");
}
__device__ __forceinline__ void ldm_x4(uint32_t& r0, uint32_t& r1, uint32_t& r2, uint32_t& r3,
                                       uint32_t addr) {
    asm volatile("ldmatrix.sync.aligned.m8n8.x4.shared.b16 {%0,%1,%2,%3}, [%4];"
                 : "=r"(r0), "=r"(r1), "=r"(r2), "=r"(r3) : "r"(addr));
}
__device__ __forceinline__ void mma_bf16(float& c0, float& c1, float& c2, float& c3,
                                         uint32_t a0, uint32_t a1, uint32_t a2, uint32_t a3,
                                         uint32_t b0, uint32_t b1) {
    asm volatile("mma.sync.aligned.m16n8k16.row.col.f32.bf16.bf16.f32 "
                 "{%0,%1,%2,%3}, {%4,%5,%6,%7}, {%8,%9}, {%0,%1,%2,%3};"
                 : "+f"(c0), "+f"(c1), "+f"(c2), "+f"(c3)
                 : "r"(a0), "r"(a1), "r"(a2), "r"(a3), "r"(b0), "r"(b1));
}

// Packed f32x2 helpers (sm_100+ dual-FMA path; ptxas never emits from C++)
__device__ __forceinline__ uint64_t pack2(float lo, float hi) {
    uint64_t r;
    asm("mov.b64 %0, {%1, %2};" : "=l"(r) : "f"(lo), "f"(hi));
    return r;
}
__device__ __forceinline__ void unpack2(float& lo, float& hi, uint64_t v) {
    asm("mov.b64 {%0, %1}, %2;" : "=f"(lo), "=f"(hi) : "l"(v));
}
__device__ __forceinline__ void ffma2(uint64_t& d, uint64_t a, uint64_t b) {
    asm("fma.rn.f32x2 %0, %1, %2, %0;" : "+l"(d) : "l"(a), "l"(b));
}

__device__ __forceinline__ void split_bf16(float v, __nv_bfloat16& hi, __nv_bfloat16& lo) {
    hi = __float2bfloat16_rn(v);
    lo = __float2bfloat16_rn(v - __bfloat162float(hi));
}

// SW128 swizzled byte offset for (row r [128B rows], 16B segment seg)
__device__ __forceinline__ uint32_t swz(int r, int seg) {
    return (uint32_t)(r * 128 + ((seg * 16) ^ ((r & 7) * 16)));
}

// ---------------------------------------------------------------------------
// Kernel 0: transpose+split weights:  Bt[n][k] = W[k][n], hi/lo bf16.
// Smem-tiled transpose, coalesced on both sides. Grid (KDIM/32, COUT/32).
// ---------------------------------------------------------------------------
__global__ void __launch_bounds__(256) kp_bprep_kernel(const float* __restrict__ W)
{
    __shared__ float tile[32][33];
    int k0 = blockIdx.x * 32;
    int n0 = blockIdx.y * 32;
    int tx = threadIdx.x & 31;
    int ty = threadIdx.x >> 5;      // 0..7

    #pragma unroll
    for (int j = 0; j < 4; ++j)
        tile[ty + 8 * j][tx] = W[(size_t)(k0 + ty + 8 * j) * COUT + n0 + tx];
    __syncthreads();

    #pragma unroll
    for (int j = 0; j < 4; ++j) {
        int n = n0 + ty + 8 * j;
        float v = tile[tx][ty + 8 * j];
        __nv_bfloat16 hi, lo;
        split_bf16(v, hi, lo);
        g_Bhi[(size_t)n * KDIM + k0 + tx] = hi;
        g_Blo[(size_t)n * KDIM + k0 + tx] = lo;
    }
}

// ---------------------------------------------------------------------------
// Kernel 1: influence weighting + neighbor aggregation. Warp-per-query.
// Inner loop uses packed fma.rn.f32x2 over kernel-point PAIRS:
//   acc2[p][c] = {acc[2p][c], acc[2p+1][c]},  w-pairs load as 64-bit lanes.
// k padded to 16 (w[15] = 0), so 8 clean pairs.
// ---------------------------------------------------------------------------
__global__ void __launch_bounds__(256) kp_weight_kernel(
    const float* __restrict__ q_pts,    // [N,3]
    const float* __restrict__ s_pts,    // [Ns,3]
    const int*   __restrict__ nb,       // [N,H]
    const float* __restrict__ x,        // [Ns,CIN]
    const float* __restrict__ kp,       // [KPTS,3]
    int N, int Ns)
{
    int wid  = threadIdx.x >> 5;
    int lane = threadIdx.x & 31;
    int n    = blockIdx.x * 8 + wid;

    __shared__ float s_kp[48];
    __shared__ float s_w[8][H][16];
    __shared__ int   s_idx[8][H];

    if (threadIdx.x < KPTS * 3) s_kp[threadIdx.x] = kp[threadIdx.x];
    __syncthreads();

    if (n < N) {
        float qx = q_pts[n * 3 + 0];
        float qy = q_pts[n * 3 + 1];
        float qz = q_pts[n * 3 + 2];

        for (int h = lane; h < H; h += 32) {
            int idx = nb[(size_t)n * H + h];
            bool valid = ((unsigned)idx < (unsigned)Ns);
            int safe = valid ? idx : 0;
            s_idx[wid][h] = safe;
            float px = s_pts[(size_t)safe * 3 + 0] - qx;
            float py = s_pts[(size_t)safe * 3 + 1] - qy;
            float pz = s_pts[(size_t)safe * 3 + 2] - qz;
            #pragma unroll
            for (int k = 0; k < KPTS; k++) {
                float dx = px - s_kp[k * 3 + 0];
                float dy = py - s_kp[k * 3 + 1];
                float dz = pz - s_kp[k * 3 + 2];
                float d2 = dx * dx + dy * dy + dz * dz;
                float w  = fmaxf(1.0f - sqrtf(d2) * KP_EXTENT_INV, 0.0f);
                s_w[wid][h][k] = valid ? w : 0.0f;
            }
            s_w[wid][h][15] = 0.0f;
        }
        __syncwarp();

        // acc2[p][c]: packed pair {k=2p, k=2p+1} for channel c (c = 4*lane..+3)
        uint64_t acc2[8][4];
        #pragma unroll
        for (int p = 0; p < 8; p++)
            #pragma unroll
            for (int c = 0; c < 4; c++) acc2[p][c] = 0ull;

        const float* xbase = x + (lane << 2);

        #pragma unroll 4
        for (int h = 0; h < H; h++) {
            int idx = s_idx[wid][h];
            float4 f = *(const float4*)(xbase + (size_t)idx * CIN);

            // w-pairs: 16 floats = 8 packed f32x2, read as 64-bit lanes
            const ulonglong2* wp = (const ulonglong2*)s_w[wid][h];
            ulonglong2 w01 = wp[0];   // pairs 0,1
            ulonglong2 w23 = wp[1];   // pairs 2,3
            ulonglong2 w45 = wp[2];   // pairs 4,5
            ulonglong2 w67 = wp[3];   // pairs 6,7
            uint64_t wpair[8] = { w01.x, w01.y, w23.x, w23.y,
                                  w45.x, w45.y, w67.x, w67.y };

            // Broadcast-pack each channel value (ALU pipe, overlaps FMA)
            uint64_t f2[4];
            f2[0] = pack2(f.x, f.x);
            f2[1] = pack2(f.y, f.y);
            f2[2] = pack2(f.z, f.z);
            f2[3] = pack2(f.w, f.w);

            #pragma unroll
            for (int p = 0; p < 8; p++) {
                ffma2(acc2[p][0], wpair[p], f2[0]);
                ffma2(acc2[p][1], wpair[p], f2[1]);
                ffma2(acc2[p][2], wpair[p], f2[2]);
                ffma2(acc2[p][3], wpair[p], f2[3]);
            }
        }

        // Unpack, split to bf16 hi/lo, store.
        size_t rowoff = (size_t)n * KDIM + (lane << 2);
        #pragma unroll
        for (int p = 0; p < 8; p++) {
            float e0, e1, o0, o1, e2, e3, o2, o3;
            unpack2(e0, o0, acc2[p][0]);
            unpack2(e1, o1, acc2[p][1]);
            unpack2(e2, o2, acc2[p][2]);
            unpack2(e3, o3, acc2[p][3]);

            // even k = 2p
            {
                int k = 2 * p;
                __nv_bfloat16 h0, h1, h2, h3, l0, l1, l2, l3;
                split_bf16(e0, h0, l0); split_bf16(e1, h1, l1);
                split_bf16(e2, h2, l2); split_bf16(e3, h3, l3);
                ushort4 vh = make_ushort4(__bfloat16_as_ushort(h0), __bfloat16_as_ushort(h1),
                                          __bfloat16_as_ushort(h2), __bfloat16_as_ushort(h3));
                ushort4 vl = make_ushort4(__bfloat16_as_ushort(l0), __bfloat16_as_ushort(l1),
                                          __bfloat16_as_ushort(l2), __bfloat16_as_ushort(l3));
                *(ushort4*)(g_Ahi + rowoff + (size_t)k * CIN) = vh;
                *(ushort4*)(g_Alo + rowoff + (size_t)k * CIN) = vl;
            }
            // odd k = 2p+1 (skip k=15 pad)
            if (p < 7) {
                int k = 2 * p + 1;
                __nv_bfloat16 h0, h1, h2, h3, l0, l1, l2, l3;
                split_bf16(o0, h0, l0); split_bf16(o1, h1, l1);
                split_bf16(o2, h2, l2); split_bf16(o3, h3, l3);
                ushort4 vh = make_ushort4(__bfloat16_as_ushort(h0), __bfloat16_as_ushort(h1),
                                          __bfloat16_as_ushort(h2), __bfloat16_as_ushort(h3));
                ushort4 vl = make_ushort4(__bfloat16_as_ushort(l0), __bfloat16_as_ushort(l1),
                                          __bfloat16_as_ushort(l2), __bfloat16_as_ushort(l3));
                *(ushort4*)(g_Ahi + rowoff + (size_t)k * CIN) = vh;
                *(ushort4*)(g_Alo + rowoff + (size_t)k * CIN) = vl;
            }
        }
    }
}

// ---------------------------------------------------------------------------
// Kernel 2: mma.sync bf16 split GEMM (unchanged from R7 — proven).
//   C[N,128] = Ahi·Bhi^T + Ahi·Blo^T + Alo·Bhi^T  (fp32 register accumulate)
// CTA: 64(M) x 128(N), 8 warps (2 M x 4 N), warp tile 32x32.
// ---------------------------------------------------------------------------
#define KC      64
#define CHUNKS  (KDIM / KC)    // 30
#define SA_H  0
#define SA_L  8192
#define SB_H  16384
#define SB_L  32768
#define ST_BYTES 49152
#define SMEM_TOTAL (2 * ST_BYTES)   // 96 KB

__global__ void __launch_bounds__(256, 2) kp_mma_gemm_kernel(float* __restrict__ C, int N)
{
    extern __shared__ char smem[];
    uint32_t sbase = smem_u32(smem);
    int tid  = threadIdx.x;
    int wid  = tid >> 5;
    int lane = tid & 31;
    int m0   = blockIdx.x * 64;

    int wm = wid & 1;
    int wn = wid >> 1;

    int seg = tid & 7;
    int rb  = tid >> 3;

    const __nv_bfloat16* Ah = g_Ahi;
    const __nv_bfloat16* Al = g_Alo;
    const __nv_bfloat16* Bh = g_Bhi;
    const __nv_bfloat16* Bl = g_Blo;

    float acc[2][4][4];
    #pragma unroll
    for (int i = 0; i < 2; i++)
        #pragma unroll
        for (int j = 0; j < 4; j++)
            #pragma unroll
            for (int q = 0; q < 4; q++) acc[i][j][q] = 0.0f;

    auto load_chunk = [&](int stage, int c) {
        uint32_t sb = sbase + stage * ST_BYTES;
        size_t c0 = (size_t)c * KC + (size_t)seg * 8;
        #pragma unroll
        for (int g = 0; g < 2; ++g) {
            int r  = g * 32 + rb;
            int ra = m0 + r; if (ra >= N) ra = N - 1;
            uint32_t off = swz(r, seg);
            cp_async16(sb + SA_H + off, Ah + (size_t)ra * KDIM + c0);
            cp_async16(sb + SA_L + off, Al + (size_t)ra * KDIM + c0);
        }
        #pragma unroll
        for (int g = 0; g < 4; ++g) {
            int r = g * 32 + rb;
            uint32_t off = swz(r, seg);
            cp_async16(sb + SB_H + off, Bh + (size_t)r * KDIM + c0);
            cp_async16(sb + SB_L + off, Bl + (size_t)r * KDIM + c0);
        }
        cp_async_commit();
    };

    int a_r15 = lane & 15;
    int a_kx  = lane >> 4;
    int b_r   = ((lane >> 4) << 3) + (lane & 7);
    int b_kx  = (lane >> 3) & 1;

    load_chunk(0, 0);

    for (int c = 0; c < CHUNKS; ++c) {
        int cur = c & 1;
        if (c + 1 < CHUNKS) load_chunk(cur ^ 1, c + 1);

        if (c + 1 < CHUNKS) cp_async_wait<1>();
        else                cp_async_wait<0>();
        __syncthreads();

        uint32_t sb = sbase + cur * ST_BYTES;

        #pragma unroll
        for (int ks = 0; ks < 4; ++ks) {
            uint32_t ah[2][4], al[2][4];
            #pragma unroll
            for (int mt = 0; mt < 2; ++mt) {
                int r  = wm * 32 + mt * 16 + a_r15;
                int sg = ks * 2 + a_kx;
                uint32_t off = swz(r, sg);
                ldm_x4(ah[mt][0], ah[mt][1], ah[mt][2], ah[mt][3], sb + SA_H + off);
                ldm_x4(al[mt][0], al[mt][1], al[mt][2], al[mt][3], sb + SA_L + off);
            }
            uint32_t bh[4][2], bl[4][2];
            #pragma unroll
            for (int nt2 = 0; nt2 < 2; ++nt2) {
                int r  = wn * 32 + nt2 * 16 + b_r;
                int sg = ks * 2 + b_kx;
                uint32_t off = swz(r, sg);
                uint32_t r0, r1, r2, r3;
                ldm_x4(r0, r1, r2, r3, sb + SB_H + off);
                bh[nt2 * 2 + 0][0] = r0; bh[nt2 * 2 + 0][1] = r1;
                bh[nt2 * 2 + 1][0] = r2; bh[nt2 * 2 + 1][1] = r3;
                ldm_x4(r0, r1, r2, r3, sb + SB_L + off);
                bl[nt2 * 2 + 0][0] = r0; bl[nt2 * 2 + 0][1] = r1;
                bl[nt2 * 2 + 1][0] = r2; bl[nt2 * 2 + 1][1] = r3;
            }
            #pragma unroll
            for (int mt = 0; mt < 2; ++mt)
                #pragma unroll
                for (int nt = 0; nt < 4; ++nt) {
                    float* cc = acc[mt][nt];
                    mma_bf16(cc[0], cc[1], cc[2], cc[3],
                             ah[mt][0], ah[mt][1], ah[mt][2], ah[mt][3],
                             bh[nt][0], bh[nt][1]);
                    mma_bf16(cc[0], cc[1], cc[2], cc[3],
                             ah[mt][0], ah[mt][1], ah[mt][2], ah[mt][3],
                             bl[nt][0], bl[nt][1]);
                    mma_bf16(cc[0], cc[1], cc[2], cc[3],
                             al[mt][0], al[mt][1], al[mt][2], al[mt][3],
                             bh[nt][0], bh[nt][1]);
                }
        }
        __syncthreads();
    }

    int tq = lane >> 2;
    int tr = (lane & 3) * 2;
    #pragma unroll
    for (int mt = 0; mt < 2; ++mt) {
        #pragma unroll
        for (int nt = 0; nt < 4; ++nt) {
            int gm = m0 + wm * 32 + mt * 16 + tq;
            int gn = wn * 32 + nt * 8 + tr;
            float* cc = acc[mt][nt];
            if (gm < N)     *(float2*)&C[(size_t)gm * COUT + gn]       = make_float2(cc[0], cc[1]);
            if (gm + 8 < N) *(float2*)&C[(size_t)(gm + 8) * COUT + gn] = make_float2(cc[2], cc[3]);
        }
    }
}

// ---------------------------------------------------------------------------
// kernel_launch
// ---------------------------------------------------------------------------
extern "C" void kernel_launch(void* const* d_in, const int* in_sizes, int n_in,
                              void* d_out, int out_size)
{
    const float* q_pts = (const float*)d_in[0];
    const float* s_pts = (const float*)d_in[1];
    const int*   nb    = (const int*)d_in[2];
    const float* x     = (const float*)d_in[3];
    const float* kp    = (const float*)d_in[4];
    const float* w     = (const float*)d_in[5];
    float*       out   = (float*)d_out;

    int N  = in_sizes[0] / 3;
    int Ns = in_sizes[1] / 3;

    static int smem_set = 0;
    if (!smem_set) {
        cudaFuncSetAttribute(kp_mma_gemm_kernel,
                             cudaFuncAttributeMaxDynamicSharedMemorySize, SMEM_TOTAL);
        smem_set = 1;
    }

    dim3 bp_grid(KDIM / 32, COUT / 32);
    kp_bprep_kernel<<<bp_grid, 256>>>(w);

    int grid1 = (N + 7) / 8;
    kp_weight_kernel<<<grid1, 256>>>(q_pts, s_pts, nb, x, kp, N, Ns);

    int grid2 = (N + 63) / 64;
    kp_mma_gemm_kernel<<<grid2, 256, SMEM_TOTAL>>>(out, N);
}

// round 9
// speedup vs baseline: 1.8272x; 1.8272x over previous
#include <cuda_runtime.h>
#include <cuda_bf16.h>
#include <cstdint>

// Problem constants (fixed shapes from the reference)
#define H     40
#define KPTS  15
#define CIN   128
#define COUT  128
#define NMAX  20000
#define KDIM  (KPTS * CIN)   // 1920
#define KP_EXTENT_INV (1.0f / 1.2f)

// ---------------------------------------------------------------------------
// Static scratch: split-bf16 operands.
// A = weighted [N, 1920] as hi+lo bf16; B = weights^T [128, 1920] as hi+lo.
// ---------------------------------------------------------------------------
__device__ __nv_bfloat16 g_Ahi[(size_t)NMAX * KDIM];
__device__ __nv_bfloat16 g_Alo[(size_t)NMAX * KDIM];
__device__ __nv_bfloat16 g_Bhi[(size_t)COUT * KDIM];
__device__ __nv_bfloat16 g_Blo[(size_t)COUT * KDIM];

// ---------------------------------------------------------------------------
// PTX helpers (baseline sm_80+ instructions — safe for compute_103)
// ---------------------------------------------------------------------------
__device__ __forceinline__ uint32_t smem_u32(const void* p) {
    uint32_t a;
    asm("{ .reg .u64 t; cvta.to.shared.u64 t, %1; cvt.u32.u64 %0, t; }" : "=r"(a) : "l"(p));
    return a;
}
__device__ __forceinline__ void cp_async16(uint32_t dst, const void* src) {
    asm volatile("cp.async.cg.shared.global [%0], [%1], 16;\n" :: "r"(dst), "l"(src) : "memory");
}
__device__ __forceinline__ void cp_async_commit() {
    asm volatile("cp.async.commit_group;" ::: "memory");
}
template <int NN>
__device__ __forceinline__ void cp_async_wait() {
    asm volatile("cp.async.wait_group %0;" :: "n"(NN) : "memory");
}
__device__ __forceinline__ void ldm_x4(uint32_t& r0, uint32_t& r1, uint32_t& r2, uint32_t& r3,
                                       uint32_t addr) {
    asm volatile("ldmatrix.sync.aligned.m8n8.x4.shared.b16 {%0,%1,%2,%3}, [%4];"
                 : "=r"(r0), "=r"(r1), "=r"(r2), "=r"(r3) : "r"(addr));
}
__device__ __forceinline__ void mma_bf16(float& c0, float& c1, float& c2, float& c3,
                                         uint32_t a0, uint32_t a1, uint32_t a2, uint32_t a3,
                                         uint32_t b0, uint32_t b1) {
    asm volatile("mma.sync.aligned.m16n8k16.row.col.f32.bf16.bf16.f32 "
                 "{%0,%1,%2,%3}, {%4,%5,%6,%7}, {%8,%9}, {%0,%1,%2,%3};"
                 : "+f"(c0), "+f"(c1), "+f"(c2), "+f"(c3)
                 : "r"(a0), "r"(a1), "r"(a2), "r"(a3), "r"(b0), "r"(b1));
}

__device__ __forceinline__ void split_bf16(float v, __nv_bfloat16& hi, __nv_bfloat16& lo) {
    hi = __float2bfloat16_rn(v);
    lo = __float2bfloat16_rn(v - __bfloat162float(hi));
}

// SW128 swizzled byte offset for (row r [128B rows], 16B segment seg)
__device__ __forceinline__ uint32_t swz(int r, int seg) {
    return (uint32_t)(r * 128 + ((seg * 16) ^ ((r & 7) * 16)));
}

// ---------------------------------------------------------------------------
// Kernel 1 (combined): blocks [0, BPREP_BLOCKS) transpose+split the weights
// (Bt[n][k] = W[k][n], hi/lo bf16, smem-tiled), remaining blocks run the
// influence weighting + neighbor aggregation (warp-per-query, R7-proven loop).
// Both paths use 256 threads; independent work, so co-running hides bprep.
// ---------------------------------------------------------------------------
#define BPREP_BLOCKS ((KDIM / 32) * (COUT / 32))   // 60 * 4 = 240

__global__ void __launch_bounds__(256) kp_prep_weight_kernel(
    const float* __restrict__ W,        // [KDIM, COUT]
    const float* __restrict__ q_pts,    // [N,3]
    const float* __restrict__ s_pts,    // [Ns,3]
    const int*   __restrict__ nb,       // [N,H]
    const float* __restrict__ x,        // [Ns,CIN]
    const float* __restrict__ kp,       // [KPTS,3]
    int N, int Ns)
{
    __shared__ float s_kp[48];
    __shared__ float s_w[8][H][16];
    __shared__ int   s_idx[8][H];
    __shared__ float tile[32][33];

    if (blockIdx.x < BPREP_BLOCKS) {
        // ---- B prep: smem-tiled transpose + hi/lo split ----
        int b  = blockIdx.x;
        int k0 = (b % (KDIM / 32)) * 32;
        int n0 = (b / (KDIM / 32)) * 32;
        int tx = threadIdx.x & 31;
        int ty = threadIdx.x >> 5;      // 0..7

        #pragma unroll
        for (int j = 0; j < 4; ++j)
            tile[ty + 8 * j][tx] = W[(size_t)(k0 + ty + 8 * j) * COUT + n0 + tx];
        __syncthreads();

        #pragma unroll
        for (int j = 0; j < 4; ++j) {
            int n = n0 + ty + 8 * j;
            float v = tile[tx][ty + 8 * j];
            __nv_bfloat16 hi, lo;
            split_bf16(v, hi, lo);
            g_Bhi[(size_t)n * KDIM + k0 + tx] = hi;
            g_Blo[(size_t)n * KDIM + k0 + tx] = lo;
        }
        return;
    }

    // ---- Influence weighting + aggregation (R7-proven) ----
    int wid  = threadIdx.x >> 5;
    int lane = threadIdx.x & 31;
    int n    = (blockIdx.x - BPREP_BLOCKS) * 8 + wid;

    if (threadIdx.x < KPTS * 3) s_kp[threadIdx.x] = kp[threadIdx.x];
    __syncthreads();

    if (n < N) {
        float qx = q_pts[n * 3 + 0];
        float qy = q_pts[n * 3 + 1];
        float qz = q_pts[n * 3 + 2];

        for (int h = lane; h < H; h += 32) {
            int idx = nb[(size_t)n * H + h];
            bool valid = ((unsigned)idx < (unsigned)Ns);
            int safe = valid ? idx : 0;
            s_idx[wid][h] = safe;
            float px = s_pts[(size_t)safe * 3 + 0] - qx;
            float py = s_pts[(size_t)safe * 3 + 1] - qy;
            float pz = s_pts[(size_t)safe * 3 + 2] - qz;
            #pragma unroll
            for (int k = 0; k < KPTS; k++) {
                float dx = px - s_kp[k * 3 + 0];
                float dy = py - s_kp[k * 3 + 1];
                float dz = pz - s_kp[k * 3 + 2];
                float d2 = dx * dx + dy * dy + dz * dz;
                float w  = fmaxf(1.0f - sqrtf(d2) * KP_EXTENT_INV, 0.0f);
                s_w[wid][h][k] = valid ? w : 0.0f;
            }
            s_w[wid][h][15] = 0.0f;
        }
        __syncwarp();

        float4 acc[KPTS];
        #pragma unroll
        for (int k = 0; k < KPTS; k++) acc[k] = make_float4(0.f, 0.f, 0.f, 0.f);

        const float* xbase = x + (lane << 2);

        #pragma unroll 4
        for (int h = 0; h < H; h++) {
            int idx = s_idx[wid][h];
            float4 f = *(const float4*)(xbase + (size_t)idx * CIN);
            float wk[16];
            const float4* wv = (const float4*)s_w[wid][h];
            *(float4*)&wk[0]  = wv[0];
            *(float4*)&wk[4]  = wv[1];
            *(float4*)&wk[8]  = wv[2];
            *(float4*)&wk[12] = wv[3];
            #pragma unroll
            for (int k = 0; k < KPTS; k++) {
                acc[k].x = fmaf(wk[k], f.x, acc[k].x);
                acc[k].y = fmaf(wk[k], f.y, acc[k].y);
                acc[k].z = fmaf(wk[k], f.z, acc[k].z);
                acc[k].w = fmaf(wk[k], f.w, acc[k].w);
            }
        }

        size_t rowoff = (size_t)n * KDIM + (lane << 2);
        #pragma unroll
        for (int k = 0; k < KPTS; k++) {
            __nv_bfloat16 h0, h1, h2, h3, l0, l1, l2, l3;
            split_bf16(acc[k].x, h0, l0);
            split_bf16(acc[k].y, h1, l1);
            split_bf16(acc[k].z, h2, l2);
            split_bf16(acc[k].w, h3, l3);
            ushort4 vh = make_ushort4(__bfloat16_as_ushort(h0), __bfloat16_as_ushort(h1),
                                      __bfloat16_as_ushort(h2), __bfloat16_as_ushort(h3));
            ushort4 vl = make_ushort4(__bfloat16_as_ushort(l0), __bfloat16_as_ushort(l1),
                                      __bfloat16_as_ushort(l2), __bfloat16_as_ushort(l3));
            *(ushort4*)(g_Ahi + rowoff + (size_t)k * CIN) = vh;
            *(ushort4*)(g_Alo + rowoff + (size_t)k * CIN) = vl;
        }
    }
}

// ---------------------------------------------------------------------------
// Kernel 2: mma.sync bf16 split GEMM (unchanged — proven).
//   C[N,128] = Ahi·Bhi^T + Ahi·Blo^T + Alo·Bhi^T  (fp32 register accumulate)
// CTA: 64(M) x 128(N), 8 warps (2 M x 4 N), warp tile 32x32.
// ---------------------------------------------------------------------------
#define KC      64
#define CHUNKS  (KDIM / KC)    // 30
#define SA_H  0
#define SA_L  8192
#define SB_H  16384
#define SB_L  32768
#define ST_BYTES 49152
#define SMEM_TOTAL (2 * ST_BYTES)   // 96 KB

__global__ void __launch_bounds__(256, 2) kp_mma_gemm_kernel(float* __restrict__ C, int N)
{
    extern __shared__ char smem[];
    uint32_t sbase = smem_u32(smem);
    int tid  = threadIdx.x;
    int wid  = tid >> 5;
    int lane = tid & 31;
    int m0   = blockIdx.x * 64;

    int wm = wid & 1;
    int wn = wid >> 1;

    int seg = tid & 7;
    int rb  = tid >> 3;

    const __nv_bfloat16* Ah = g_Ahi;
    const __nv_bfloat16* Al = g_Alo;
    const __nv_bfloat16* Bh = g_Bhi;
    const __nv_bfloat16* Bl = g_Blo;

    float acc[2][4][4];
    #pragma unroll
    for (int i = 0; i < 2; i++)
        #pragma unroll
        for (int j = 0; j < 4; j++)
            #pragma unroll
            for (int q = 0; q < 4; q++) acc[i][j][q] = 0.0f;

    auto load_chunk = [&](int stage, int c) {
        uint32_t sb = sbase + stage * ST_BYTES;
        size_t c0 = (size_t)c * KC + (size_t)seg * 8;
        #pragma unroll
        for (int g = 0; g < 2; ++g) {
            int r  = g * 32 + rb;
            int ra = m0 + r; if (ra >= N) ra = N - 1;
            uint32_t off = swz(r, seg);
            cp_async16(sb + SA_H + off, Ah + (size_t)ra * KDIM + c0);
            cp_async16(sb + SA_L + off, Al + (size_t)ra * KDIM + c0);
        }
        #pragma unroll
        for (int g = 0; g < 4; ++g) {
            int r = g * 32 + rb;
            uint32_t off = swz(r, seg);
            cp_async16(sb + SB_H + off, Bh + (size_t)r * KDIM + c0);
            cp_async16(sb + SB_L + off, Bl + (size_t)r * KDIM + c0);
        }
        cp_async_commit();
    };

    int a_r15 = lane & 15;
    int a_kx  = lane >> 4;
    int b_r   = ((lane >> 4) << 3) + (lane & 7);
    int b_kx  = (lane >> 3) & 1;

    load_chunk(0, 0);

    for (int c = 0; c < CHUNKS; ++c) {
        int cur = c & 1;
        if (c + 1 < CHUNKS) load_chunk(cur ^ 1, c + 1);

        if (c + 1 < CHUNKS) cp_async_wait<1>();
        else                cp_async_wait<0>();
        __syncthreads();

        uint32_t sb = sbase + cur * ST_BYTES;

        #pragma unroll
        for (int ks = 0; ks < 4; ++ks) {
            uint32_t ah[2][4], al[2][4];
            #pragma unroll
            for (int mt = 0; mt < 2; ++mt) {
                int r  = wm * 32 + mt * 16 + a_r15;
                int sg = ks * 2 + a_kx;
                uint32_t off = swz(r, sg);
                ldm_x4(ah[mt][0], ah[mt][1], ah[mt][2], ah[mt][3], sb + SA_H + off);
                ldm_x4(al[mt][0], al[mt][1], al[mt][2], al[mt][3], sb + SA_L + off);
            }
            uint32_t bh[4][2], bl[4][2];
            #pragma unroll
            for (int nt2 = 0; nt2 < 2; ++nt2) {
                int r  = wn * 32 + nt2 * 16 + b_r;
                int sg = ks * 2 + b_kx;
                uint32_t off = swz(r, sg);
                uint32_t r0, r1, r2, r3;
                ldm_x4(r0, r1, r2, r3, sb + SB_H + off);
                bh[nt2 * 2 + 0][0] = r0; bh[nt2 * 2 + 0][1] = r1;
                bh[nt2 * 2 + 1][0] = r2; bh[nt2 * 2 + 1][1] = r3;
                ldm_x4(r0, r1, r2, r3, sb + SB_L + off);
                bl[nt2 * 2 + 0][0] = r0; bl[nt2 * 2 + 0][1] = r1;
                bl[nt2 * 2 + 1][0] = r2; bl[nt2 * 2 + 1][1] = r3;
            }
            #pragma unroll
            for (int mt = 0; mt < 2; ++mt)
                #pragma unroll
                for (int nt = 0; nt < 4; ++nt) {
                    float* cc = acc[mt][nt];
                    mma_bf16(cc[0], cc[1], cc[2], cc[3],
                             ah[mt][0], ah[mt][1], ah[mt][2], ah[mt][3],
                             bh[nt][0], bh[nt][1]);
                    mma_bf16(cc[0], cc[1], cc[2], cc[3],
                             ah[mt][0], ah[mt][1], ah[mt][2], ah[mt][3],
                             bl[nt][0], bl[nt][1]);
                    mma_bf16(cc[0], cc[1], cc[2], cc[3],
                             al[mt][0], al[mt][1], al[mt][2], al[mt][3],
                             bh[nt][0], bh[nt][1]);
                }
        }
        __syncthreads();
    }

    int tq = lane >> 2;
    int tr = (lane & 3) * 2;
    #pragma unroll
    for (int mt = 0; mt < 2; ++mt) {
        #pragma unroll
        for (int nt = 0; nt < 4; ++nt) {
            int gm = m0 + wm * 32 + mt * 16 + tq;
            int gn = wn * 32 + nt * 8 + tr;
            float* cc = acc[mt][nt];
            if (gm < N)     *(float2*)&C[(size_t)gm * COUT + gn]       = make_float2(cc[0], cc[1]);
            if (gm + 8 < N) *(float2*)&C[(size_t)(gm + 8) * COUT + gn] = make_float2(cc[2], cc[3]);
        }
    }
}

// ---------------------------------------------------------------------------
// kernel_launch
// Inputs: q_pts [N,3] f32, s_pts [Ns,3] f32, neighb_inds [N,H] i32,
// x [Ns,CIN] f32, kernel_points [KPTS,3] f32, weights [KPTS,CIN,COUT] f32.
// Output: [N,COUT] f32.
// ---------------------------------------------------------------------------
extern "C" void kernel_launch(void* const* d_in, const int* in_sizes, int n_in,
                              void* d_out, int out_size)
{
    const float* q_pts = (const float*)d_in[0];
    const float* s_pts = (const float*)d_in[1];
    const int*   nb    = (const int*)d_in[2];
    const float* x     = (const float*)d_in[3];
    const float* kp    = (const float*)d_in[4];
    const float* w     = (const float*)d_in[5];
    float*       out   = (float*)d_out;

    int N  = in_sizes[0] / 3;
    int Ns = in_sizes[1] / 3;

    static int smem_set = 0;
    if (!smem_set) {
        cudaFuncSetAttribute(kp_mma_gemm_kernel,
                             cudaFuncAttributeMaxDynamicSharedMemorySize, SMEM_TOTAL);
        smem_set = 1;
    }

    int grid1 = BPREP_BLOCKS + (N + 7) / 8;
    kp_prep_weight_kernel<<<grid1, 256>>>(w, q_pts, s_pts, nb, x, kp, N, Ns);

    int grid2 = (N + 63) / 64;
    kp_mma_gemm_kernel<<<grid2, 256, SMEM_TOTAL>>>(out, N);
}

// round 10
// speedup vs baseline: 1.9441x; 1.0640x over previous
#include <cuda_runtime.h>
#include <cuda_bf16.h>
#include <cstdint>

// Problem constants (fixed shapes from the reference)
#define H     40
#define KPTS  15
#define CIN   128
#define COUT  128
#define NMAX  20000
#define KDIM  (KPTS * CIN)   // 1920
#define KP_EXTENT_INV (1.0f / 1.2f)

// ---------------------------------------------------------------------------
// Static scratch: split-bf16 operands + split-K partial outputs.
// ---------------------------------------------------------------------------
__device__ __nv_bfloat16 g_Ahi[(size_t)NMAX * KDIM];
__device__ __nv_bfloat16 g_Alo[(size_t)NMAX * KDIM];
__device__ __nv_bfloat16 g_Bhi[(size_t)COUT * KDIM];
__device__ __nv_bfloat16 g_Blo[(size_t)COUT * KDIM];
__device__ float         g_Cpart[2][(size_t)NMAX * COUT];   // split-K partials

// ---------------------------------------------------------------------------
// PTX helpers (baseline sm_80+ instructions — safe for compute_103)
// ---------------------------------------------------------------------------
__device__ __forceinline__ uint32_t smem_u32(const void* p) {
    uint32_t a;
    asm("{ .reg .u64 t; cvta.to.shared.u64 t, %1; cvt.u32.u64 %0, t; }" : "=r"(a) : "l"(p));
    return a;
}
__device__ __forceinline__ void cp_async16(uint32_t dst, const void* src) {
    asm volatile("cp.async.cg.shared.global [%0], [%1], 16;\n" :: "r"(dst), "l"(src) : "memory");
}
__device__ __forceinline__ void cp_async_commit() {
    asm volatile("cp.async.commit_group;" ::: "memory");
}
template <int NN>
__device__ __forceinline__ void cp_async_wait() {
    asm volatile("cp.async.wait_group %0;" :: "n"(NN) : "memory");
}
__device__ __forceinline__ void ldm_x4(uint32_t& r0, uint32_t& r1, uint32_t& r2, uint32_t& r3,
                                       uint32_t addr) {
    asm volatile("ldmatrix.sync.aligned.m8n8.x4.shared.b16 {%0,%1,%2,%3}, [%4];"
                 : "=r"(r0), "=r"(r1), "=r"(r2), "=r"(r3) : "r"(addr));
}
__device__ __forceinline__ void mma_bf16(float& c0, float& c1, float& c2, float& c3,
                                         uint32_t a0, uint32_t a1, uint32_t a2, uint32_t a3,
                                         uint32_t b0, uint32_t b1) {
    asm volatile("mma.sync.aligned.m16n8k16.row.col.f32.bf16.bf16.f32 "
                 "{%0,%1,%2,%3}, {%4,%5,%6,%7}, {%8,%9}, {%0,%1,%2,%3};"
                 : "+f"(c0), "+f"(c1), "+f"(c2), "+f"(c3)
                 : "r"(a0), "r"(a1), "r"(a2), "r"(a3), "r"(b0), "r"(b1));
}

__device__ __forceinline__ void split_bf16(float v, __nv_bfloat16& hi, __nv_bfloat16& lo) {
    hi = __float2bfloat16_rn(v);
    lo = __float2bfloat16_rn(v - __bfloat162float(hi));
}

// SW128 swizzled byte offset for (row r [128B rows], 16B segment seg)
__device__ __forceinline__ uint32_t swz(int r, int seg) {
    return (uint32_t)(r * 128 + ((seg * 16) ^ ((r & 7) * 16)));
}

// ---------------------------------------------------------------------------
// Kernel 1 (combined): blocks [0, BPREP_BLOCKS) transpose+split the weights,
// remaining blocks run influence weighting + neighbor aggregation
// (warp-per-query, proven loop). Both paths use 256 threads.
// ---------------------------------------------------------------------------
#define BPREP_BLOCKS ((KDIM / 32) * (COUT / 32))   // 60 * 4 = 240

__global__ void __launch_bounds__(256) kp_prep_weight_kernel(
    const float* __restrict__ W,        // [KDIM, COUT]
    const float* __restrict__ q_pts,    // [N,3]
    const float* __restrict__ s_pts,    // [Ns,3]
    const int*   __restrict__ nb,       // [N,H]
    const float* __restrict__ x,        // [Ns,CIN]
    const float* __restrict__ kp,       // [KPTS,3]
    int N, int Ns)
{
    __shared__ float s_kp[48];
    __shared__ float s_w[8][H][16];
    __shared__ int   s_idx[8][H];
    __shared__ float tile[32][33];

    if (blockIdx.x < BPREP_BLOCKS) {
        // ---- B prep: smem-tiled transpose + hi/lo split ----
        int b  = blockIdx.x;
        int k0 = (b % (KDIM / 32)) * 32;
        int n0 = (b / (KDIM / 32)) * 32;
        int tx = threadIdx.x & 31;
        int ty = threadIdx.x >> 5;      // 0..7

        #pragma unroll
        for (int j = 0; j < 4; ++j)
            tile[ty + 8 * j][tx] = W[(size_t)(k0 + ty + 8 * j) * COUT + n0 + tx];
        __syncthreads();

        #pragma unroll
        for (int j = 0; j < 4; ++j) {
            int n = n0 + ty + 8 * j;
            float v = tile[tx][ty + 8 * j];
            __nv_bfloat16 hi, lo;
            split_bf16(v, hi, lo);
            g_Bhi[(size_t)n * KDIM + k0 + tx] = hi;
            g_Blo[(size_t)n * KDIM + k0 + tx] = lo;
        }
        return;
    }

    // ---- Influence weighting + aggregation ----
    int wid  = threadIdx.x >> 5;
    int lane = threadIdx.x & 31;
    int n    = (blockIdx.x - BPREP_BLOCKS) * 8 + wid;

    if (threadIdx.x < KPTS * 3) s_kp[threadIdx.x] = kp[threadIdx.x];
    __syncthreads();

    if (n < N) {
        float qx = q_pts[n * 3 + 0];
        float qy = q_pts[n * 3 + 1];
        float qz = q_pts[n * 3 + 2];

        for (int h = lane; h < H; h += 32) {
            int idx = nb[(size_t)n * H + h];
            bool valid = ((unsigned)idx < (unsigned)Ns);
            int safe = valid ? idx : 0;
            s_idx[wid][h] = safe;
            float px = s_pts[(size_t)safe * 3 + 0] - qx;
            float py = s_pts[(size_t)safe * 3 + 1] - qy;
            float pz = s_pts[(size_t)safe * 3 + 2] - qz;
            #pragma unroll
            for (int k = 0; k < KPTS; k++) {
                float dx = px - s_kp[k * 3 + 0];
                float dy = py - s_kp[k * 3 + 1];
                float dz = pz - s_kp[k * 3 + 2];
                float d2 = dx * dx + dy * dy + dz * dz;
                float w  = fmaxf(1.0f - sqrtf(d2) * KP_EXTENT_INV, 0.0f);
                s_w[wid][h][k] = valid ? w : 0.0f;
            }
            s_w[wid][h][15] = 0.0f;
        }
        __syncwarp();

        float4 acc[KPTS];
        #pragma unroll
        for (int k = 0; k < KPTS; k++) acc[k] = make_float4(0.f, 0.f, 0.f, 0.f);

        const float* xbase = x + (lane << 2);

        #pragma unroll 4
        for (int h = 0; h < H; h++) {
            int idx = s_idx[wid][h];
            float4 f = *(const float4*)(xbase + (size_t)idx * CIN);
            float wk[16];
            const float4* wv = (const float4*)s_w[wid][h];
            *(float4*)&wk[0]  = wv[0];
            *(float4*)&wk[4]  = wv[1];
            *(float4*)&wk[8]  = wv[2];
            *(float4*)&wk[12] = wv[3];
            #pragma unroll
            for (int k = 0; k < KPTS; k++) {
                acc[k].x = fmaf(wk[k], f.x, acc[k].x);
                acc[k].y = fmaf(wk[k], f.y, acc[k].y);
                acc[k].z = fmaf(wk[k], f.z, acc[k].z);
                acc[k].w = fmaf(wk[k], f.w, acc[k].w);
            }
        }

        size_t rowoff = (size_t)n * KDIM + (lane << 2);
        #pragma unroll
        for (int k = 0; k < KPTS; k++) {
            __nv_bfloat16 h0, h1, h2, h3, l0, l1, l2, l3;
            split_bf16(acc[k].x, h0, l0);
            split_bf16(acc[k].y, h1, l1);
            split_bf16(acc[k].z, h2, l2);
            split_bf16(acc[k].w, h3, l3);
            ushort4 vh = make_ushort4(__bfloat16_as_ushort(h0), __bfloat16_as_ushort(h1),
                                      __bfloat16_as_ushort(h2), __bfloat16_as_ushort(h3));
            ushort4 vl = make_ushort4(__bfloat16_as_ushort(l0), __bfloat16_as_ushort(l1),
                                      __bfloat16_as_ushort(l2), __bfloat16_as_ushort(l3));
            *(ushort4*)(g_Ahi + rowoff + (size_t)k * CIN) = vh;
            *(ushort4*)(g_Alo + rowoff + (size_t)k * CIN) = vl;
        }
    }
}

// ---------------------------------------------------------------------------
// Kernel 2: mma.sync bf16 split GEMM, SPLIT-K = 2.
//   Cpart[kz][N,128] = sum over K-half kz of Ahi·Bhi^T + Ahi·Blo^T + Alo·Bhi^T
// CTA: 64(M) x 128(N), 8 warps (2 M x 4 N), warp tile 32x32.
// grid = 2 * ceil(N/64): blockIdx.x = mt*2 + kz. Each CTA does 15 K-chunks.
// ---------------------------------------------------------------------------
#define KC        64
#define CHUNKS    (KDIM / KC)        // 30
#define SPLITK    2
#define CHUNKS_PK (CHUNKS / SPLITK)  // 15
#define SA_H  0
#define SA_L  8192
#define SB_H  16384
#define SB_L  32768
#define ST_BYTES 49152
#define SMEM_TOTAL (2 * ST_BYTES)    // 96 KB

__global__ void __launch_bounds__(256, 2) kp_mma_gemm_kernel(int N)
{
    extern __shared__ char smem[];
    uint32_t sbase = smem_u32(smem);
    int tid  = threadIdx.x;
    int wid  = tid >> 5;
    int lane = tid & 31;

    int mt   = blockIdx.x >> 1;
    int kz   = blockIdx.x & 1;
    int m0   = mt * 64;
    int cbase = kz * CHUNKS_PK;

    float* Cp_out = g_Cpart[kz];

    int wm = wid & 1;
    int wn = wid >> 1;

    int seg = tid & 7;
    int rb  = tid >> 3;

    const __nv_bfloat16* Ah = g_Ahi;
    const __nv_bfloat16* Al = g_Alo;
    const __nv_bfloat16* Bh = g_Bhi;
    const __nv_bfloat16* Bl = g_Blo;

    float acc[2][4][4];
    #pragma unroll
    for (int i = 0; i < 2; i++)
        #pragma unroll
        for (int j = 0; j < 4; j++)
            #pragma unroll
            for (int q = 0; q < 4; q++) acc[i][j][q] = 0.0f;

    auto load_chunk = [&](int stage, int c) {
        uint32_t sb = sbase + stage * ST_BYTES;
        size_t c0 = (size_t)c * KC + (size_t)seg * 8;
        #pragma unroll
        for (int g = 0; g < 2; ++g) {
            int r  = g * 32 + rb;
            int ra = m0 + r; if (ra >= N) ra = N - 1;
            uint32_t off = swz(r, seg);
            cp_async16(sb + SA_H + off, Ah + (size_t)ra * KDIM + c0);
            cp_async16(sb + SA_L + off, Al + (size_t)ra * KDIM + c0);
        }
        #pragma unroll
        for (int g = 0; g < 4; ++g) {
            int r = g * 32 + rb;
            uint32_t off = swz(r, seg);
            cp_async16(sb + SB_H + off, Bh + (size_t)r * KDIM + c0);
            cp_async16(sb + SB_L + off, Bl + (size_t)r * KDIM + c0);
        }
        cp_async_commit();
    };

    int a_r15 = lane & 15;
    int a_kx  = lane >> 4;
    int b_r   = ((lane >> 4) << 3) + (lane & 7);
    int b_kx  = (lane >> 3) & 1;

    load_chunk(0, cbase);

    for (int ci = 0; ci < CHUNKS_PK; ++ci) {
        int cur = ci & 1;
        if (ci + 1 < CHUNKS_PK) load_chunk(cur ^ 1, cbase + ci + 1);

        if (ci + 1 < CHUNKS_PK) cp_async_wait<1>();
        else                    cp_async_wait<0>();
        __syncthreads();

        uint32_t sb = sbase + cur * ST_BYTES;

        #pragma unroll
        for (int ks = 0; ks < 4; ++ks) {
            uint32_t ah[2][4], al[2][4];
            #pragma unroll
            for (int mtt = 0; mtt < 2; ++mtt) {
                int r  = wm * 32 + mtt * 16 + a_r15;
                int sg = ks * 2 + a_kx;
                uint32_t off = swz(r, sg);
                ldm_x4(ah[mtt][0], ah[mtt][1], ah[mtt][2], ah[mtt][3], sb + SA_H + off);
                ldm_x4(al[mtt][0], al[mtt][1], al[mtt][2], al[mtt][3], sb + SA_L + off);
            }
            uint32_t bh[4][2], bl[4][2];
            #pragma unroll
            for (int nt2 = 0; nt2 < 2; ++nt2) {
                int r  = wn * 32 + nt2 * 16 + b_r;
                int sg = ks * 2 + b_kx;
                uint32_t off = swz(r, sg);
                uint32_t r0, r1, r2, r3;
                ldm_x4(r0, r1, r2, r3, sb + SB_H + off);
                bh[nt2 * 2 + 0][0] = r0; bh[nt2 * 2 + 0][1] = r1;
                bh[nt2 * 2 + 1][0] = r2; bh[nt2 * 2 + 1][1] = r3;
                ldm_x4(r0, r1, r2, r3, sb + SB_L + off);
                bl[nt2 * 2 + 0][0] = r0; bl[nt2 * 2 + 0][1] = r1;
                bl[nt2 * 2 + 1][0] = r2; bl[nt2 * 2 + 1][1] = r3;
            }
            #pragma unroll
            for (int mtt = 0; mtt < 2; ++mtt)
                #pragma unroll
                for (int nt = 0; nt < 4; ++nt) {
                    float* cc = acc[mtt][nt];
                    mma_bf16(cc[0], cc[1], cc[2], cc[3],
                             ah[mtt][0], ah[mtt][1], ah[mtt][2], ah[mtt][3],
                             bh[nt][0], bh[nt][1]);
                    mma_bf16(cc[0], cc[1], cc[2], cc[3],
                             ah[mtt][0], ah[mtt][1], ah[mtt][2], ah[mtt][3],
                             bl[nt][0], bl[nt][1]);
                    mma_bf16(cc[0], cc[1], cc[2], cc[3],
                             al[mtt][0], al[mtt][1], al[mtt][2], al[mtt][3],
                             bh[nt][0], bh[nt][1]);
                }
        }
        __syncthreads();
    }

    int tq = lane >> 2;
    int tr = (lane & 3) * 2;
    #pragma unroll
    for (int mtt = 0; mtt < 2; ++mtt) {
        #pragma unroll
        for (int nt = 0; nt < 4; ++nt) {
            int gm = m0 + wm * 32 + mtt * 16 + tq;
            int gn = wn * 32 + nt * 8 + tr;
            float* cc = acc[mtt][nt];
            if (gm < N)     *(float2*)&Cp_out[(size_t)gm * COUT + gn]       = make_float2(cc[0], cc[1]);
            if (gm + 8 < N) *(float2*)&Cp_out[(size_t)(gm + 8) * COUT + gn] = make_float2(cc[2], cc[3]);
        }
    }
}

// ---------------------------------------------------------------------------
// Kernel 3: combine split-K partials.  out = p0 + p1  (float4 vectorized)
// ---------------------------------------------------------------------------
__global__ void __launch_bounds__(256) kp_splitk_add_kernel(float* __restrict__ out, int total4)
{
    int i = blockIdx.x * blockDim.x + threadIdx.x;
    if (i < total4) {
        const float4* p0 = (const float4*)g_Cpart[0];
        const float4* p1 = (const float4*)g_Cpart[1];
        float4 a = p0[i];
        float4 b = p1[i];
        ((float4*)out)[i] = make_float4(a.x + b.x, a.y + b.y, a.z + b.z, a.w + b.w);
    }
}

// ---------------------------------------------------------------------------
// kernel_launch
// Inputs: q_pts [N,3] f32, s_pts [Ns,3] f32, neighb_inds [N,H] i32,
// x [Ns,CIN] f32, kernel_points [KPTS,3] f32, weights [KPTS,CIN,COUT] f32.
// Output: [N,COUT] f32.
// ---------------------------------------------------------------------------
extern "C" void kernel_launch(void* const* d_in, const int* in_sizes, int n_in,
                              void* d_out, int out_size)
{
    const float* q_pts = (const float*)d_in[0];
    const float* s_pts = (const float*)d_in[1];
    const int*   nb    = (const int*)d_in[2];
    const float* x     = (const float*)d_in[3];
    const float* kp    = (const float*)d_in[4];
    const float* w     = (const float*)d_in[5];
    float*       out   = (float*)d_out;

    int N  = in_sizes[0] / 3;
    int Ns = in_sizes[1] / 3;

    static int smem_set = 0;
    if (!smem_set) {
        cudaFuncSetAttribute(kp_mma_gemm_kernel,
                             cudaFuncAttributeMaxDynamicSharedMemorySize, SMEM_TOTAL);
        smem_set = 1;
    }

    int grid1 = BPREP_BLOCKS + (N + 7) / 8;
    kp_prep_weight_kernel<<<grid1, 256>>>(w, q_pts, s_pts, nb, x, kp, N, Ns);

    int mtiles = (N + 63) / 64;
    kp_mma_gemm_kernel<<<mtiles * SPLITK, 256, SMEM_TOTAL>>>(N);

    int total4 = (N * COUT) / 4;
    kp_splitk_add_kernel<<<(total4 + 255) / 256, 256>>>(out, total4);
}